// round 13
// baseline (speedup 1.0000x reference)
#include <cuda_runtime.h>
#include <cuda_fp16.h>
#include <stdint.h>

#define NN 100000
#define EE 1600000
#define ET (EE + NN)
#define NB ((NN + 1023) / 1024)   // 98 scan blocks

// ---------------- scratch (device globals; no allocations) ----------------
__device__ __align__(16) __half2 g_xh1h[(size_t)NN * 128];  // layer1 x@W1 (fp16)
__device__ __align__(16) __half  g_xh2h[(size_t)NN * 32];   // layer2 h@W2 (fp16)
__device__ float g_es1[NN * 8];
__device__ float g_ed1[NN * 8];
__device__ float g_es2[NN];
__device__ float g_ed2[NN];
__device__ int   g_deg[NN];          // zero-init at load; re-zeroed every run
__device__ int   g_rowptr[NN + 1];
__device__ int   g_cursor[NN];
__device__ int   g_adj[ET];
__device__ int   g_bsums[NB];
__device__ int   g_is64;

// ---------------- side stream for CSR/gemm1 concurrency -------------------
namespace {
struct StreamHolder {
    cudaStream_t s2;
    cudaEvent_t evFork, evJoin;
    StreamHolder() {
        cudaStreamCreateWithFlags(&s2, cudaStreamNonBlocking);
        cudaEventCreateWithFlags(&evFork, cudaEventDisableTiming);
        cudaEventCreateWithFlags(&evJoin, cudaEventDisableTiming);
    }
};
StreamHolder g_sh;
}

// ---------------- int32/int64 edge_index handling ----------------
__global__ void k_detect(const int* __restrict__ ei) {
    if (threadIdx.x == 0) {
        int nz = 0;
        for (int i = 0; i < 256; i++) nz |= ei[2 * i + 1];
        g_is64 = (nz == 0) ? 1 : 0;
    }
}

__device__ __forceinline__ int edge_idx(const void* ei, int row, int i) {
    if (g_is64) return (int)((const long long*)ei)[(size_t)row * EE + i];
    return ((const int*)ei)[(size_t)row * EE + i];
}

// ---------------- CSR build ----------------
__global__ void k_deg_count(const void* __restrict__ ei) {
    int i = blockIdx.x * blockDim.x + threadIdx.x;
    if (i < EE) atomicAdd(&g_deg[edge_idx(ei, 1, i)], 1);
}

__global__ void k_scan_block() {
    __shared__ int sh[1024];
    int i = blockIdx.x * 1024 + threadIdx.x;
    int v = 0;
    if (i < NN) {
        v = g_deg[i] + 1;      // +1 = self-loop
        g_deg[i] = 0;          // restore zero-invariant for next run
    }
    sh[threadIdx.x] = v;
    #pragma unroll
    for (int off = 1; off < 1024; off <<= 1) {
        __syncthreads();
        int x = (threadIdx.x >= off) ? sh[threadIdx.x - off] : 0;
        __syncthreads();
        sh[threadIdx.x] += x;
    }
    if (i < NN) g_rowptr[i] = sh[threadIdx.x] - v;         // exclusive
    if (threadIdx.x == 1023) g_bsums[blockIdx.x] = sh[1023];
}

__global__ void k_scan_sums() {
    __shared__ int sh[128];
    int t = threadIdx.x;
    int v = (t < NB) ? g_bsums[t] : 0;
    sh[t] = v;
    #pragma unroll
    for (int off = 1; off < 128; off <<= 1) {
        __syncthreads();
        int x = (t >= off) ? sh[t - off] : 0;
        __syncthreads();
        sh[t] += x;
    }
    if (t < NB) g_bsums[t] = sh[t] - v;                     // exclusive
}

__global__ void k_scan_add() {
    int i = blockIdx.x * 1024 + threadIdx.x;
    if (i < NN) {
        int r = g_rowptr[i] + g_bsums[blockIdx.x];
        g_rowptr[i] = r;
        g_cursor[i] = r;
    }
    if (i == 0) g_rowptr[NN] = ET;
}

__global__ void k_scatter(const void* __restrict__ ei) {
    int i = blockIdx.x * blockDim.x + threadIdx.x;
    if (i >= ET) return;
    int s, d;
    if (i < EE) { s = edge_idx(ei, 0, i); d = edge_idx(ei, 1, i); }
    else        { s = d = i - EE; }
    int pos = atomicAdd(&g_cursor[d], 1);
    g_adj[pos] = s;
}

// ---------------- GEMM1 (fp16 tensor cores, fp32 accum) + fused logits ----
__device__ __forceinline__ uint32_t pack_h2(float a, float b) {
    __half2 h = __floats2half2_rn(a, b);
    return *(uint32_t*)&h;
}

__global__ void __launch_bounds__(256, 2) k_gemm1(const float* __restrict__ X,
                                                  const float* __restrict__ W,
                                                  const float* __restrict__ as1,
                                                  const float* __restrict__ ad1) {
    __shared__ uint32_t Ast[16][136];   // [k-pair][m]; frag bank = (8kc+m)%32
    __shared__ uint32_t Bs [16][136];   // [k-pair][n]; frag bank = (8kc+n)%32
    const int bm = blockIdx.x * 128, bn = blockIdx.y * 128;
    const int tid  = threadIdx.x;
    const int warp = tid >> 5;
    const int lane = tid & 31;
    const int wm = (warp >> 2) * 64;    // warp m-offset (0/64)
    const int wn = (warp & 3) * 32;     // warp n-offset (0/32/64/96)
    const int r  = lane >> 2;           // 0..7
    const int cc = lane & 3;            // 0..3

    float c[4][4][4];                   // [mt][nt][frag]
    #pragma unroll
    for (int i = 0; i < 4; i++)
        #pragma unroll
        for (int j = 0; j < 4; j++)
            c[i][j][0] = c[i][j][1] = c[i][j][2] = c[i][j][3] = 0.f;

    const int a_lr = tid >> 3;          // A: row within 32-row pass (0..31)
    const int a_c4 = (tid & 7) * 4;     // A: float col base (16B contiguous/lane)
    const int a_kp = (tid & 7) * 2;     // A: k-pair base
    const int b_R  = tid >> 4;          // B: k-pair row (0..15)
    const int b_n0 = (tid & 15) * 4;    // B: word col base (16B contiguous/lane)

    #pragma unroll
    for (int chunk = 0; chunk < 4; chunk++) {
        const int k0 = chunk * 32;
        {   // ---- A chunk (128 x 32 fp32): coalesced 4-line LDGs ----
            #pragma unroll
            for (int p = 0; p < 4; p++) {
                const int m = p * 32 + a_lr;
                const int gm = bm + m;
                float4 v = (gm < NN)
                    ? *(const float4*)(X + (size_t)gm * 128 + k0 + a_c4)
                    : make_float4(0.f, 0.f, 0.f, 0.f);
                Ast[a_kp][m]     = pack_h2(v.x, v.y);
                Ast[a_kp + 1][m] = pack_h2(v.z, v.w);
            }
        }
        {   // ---- B chunk (32 x 128): coalesced LDGs + conflict-free STS.128
            #pragma unroll
            for (int it = 0; it < 2; it++) {
                const int n0 = b_n0 + it * 64;
                const float* w0 = W + (size_t)(k0 + 2 * b_R)     * 256 + bn + n0;
                const float* w1 = W + (size_t)(k0 + 2 * b_R + 1) * 256 + bn + n0;
                float4 x0 = *(const float4*)w0;
                float4 x1 = *(const float4*)w1;
                uint4 u;
                u.x = pack_h2(x0.x, x1.x); u.y = pack_h2(x0.y, x1.y);
                u.z = pack_h2(x0.z, x1.z); u.w = pack_h2(x0.w, x1.w);
                *(uint4*)&Bs[b_R][n0] = u;
            }
        }
        __syncthreads();
        #pragma unroll
        for (int ks = 0; ks < 2; ks++) {
            const int kk2 = ks * 8;
            uint32_t a[4][4], b[4][2];
            #pragma unroll
            for (int mt = 0; mt < 4; mt++) {
                const int mb = wm + mt * 16 + r;
                a[mt][0] = Ast[kk2 + cc][mb];
                a[mt][1] = Ast[kk2 + cc][mb + 8];
                a[mt][2] = Ast[kk2 + cc + 4][mb];
                a[mt][3] = Ast[kk2 + cc + 4][mb + 8];
            }
            #pragma unroll
            for (int nt = 0; nt < 4; nt++) {
                const int nb = wn + nt * 8 + r;
                b[nt][0] = Bs[kk2 + cc][nb];
                b[nt][1] = Bs[kk2 + cc + 4][nb];
            }
            #pragma unroll
            for (int mt = 0; mt < 4; mt++)
                #pragma unroll
                for (int nt = 0; nt < 4; nt++)
                    asm volatile(
                        "mma.sync.aligned.m16n8k16.row.col.f32.f16.f16.f32 "
                        "{%0,%1,%2,%3},{%4,%5,%6,%7},{%8,%9},{%0,%1,%2,%3};"
                        : "+f"(c[mt][nt][0]), "+f"(c[mt][nt][1]),
                          "+f"(c[mt][nt][2]), "+f"(c[mt][nt][3])
                        : "r"(a[mt][0]), "r"(a[mt][1]), "r"(a[mt][2]), "r"(a[mt][3]),
                          "r"(b[nt][0]), "r"(b[nt][1]));
        }
        __syncthreads();
    }

    // ---- fused es/ed from fp32 accumulators (this warp's n-span = 1 head) --
    const int head = (bn + wn) >> 5;
    float av[4][2], dv[4][2];
    #pragma unroll
    for (int nt = 0; nt < 4; nt++) {
        const int n = bn + wn + nt * 8 + 2 * cc;
        av[nt][0] = __ldg(&as1[n]);     av[nt][1] = __ldg(&as1[n + 1]);
        dv[nt][0] = __ldg(&ad1[n]);     dv[nt][1] = __ldg(&ad1[n + 1]);
    }
    #pragma unroll
    for (int mt = 0; mt < 4; mt++) {
        const int m0 = bm + wm + mt * 16 + r;
        const int m1 = m0 + 8;
        float es0 = 0.f, ed0 = 0.f, es1v = 0.f, ed1v = 0.f;
        #pragma unroll
        for (int nt = 0; nt < 4; nt++) {
            es0  += c[mt][nt][0] * av[nt][0] + c[mt][nt][1] * av[nt][1];
            ed0  += c[mt][nt][0] * dv[nt][0] + c[mt][nt][1] * dv[nt][1];
            es1v += c[mt][nt][2] * av[nt][0] + c[mt][nt][3] * av[nt][1];
            ed1v += c[mt][nt][2] * dv[nt][0] + c[mt][nt][3] * dv[nt][1];
        }
        #pragma unroll
        for (int off = 1; off < 4; off <<= 1) {
            es0  += __shfl_xor_sync(0xffffffffu, es0,  off);
            ed0  += __shfl_xor_sync(0xffffffffu, ed0,  off);
            es1v += __shfl_xor_sync(0xffffffffu, es1v, off);
            ed1v += __shfl_xor_sync(0xffffffffu, ed1v, off);
        }
        if (cc == 0) {
            if (m0 < NN) { g_es1[m0 * 8 + head] = es0;  g_ed1[m0 * 8 + head] = ed0; }
            if (m1 < NN) { g_es1[m1 * 8 + head] = es1v; g_ed1[m1 * 8 + head] = ed1v; }
        }
    }

    // ---- epilogue: stage 32 output rows at a time in smem, STG.128 out ----
    uint32_t* stage = &Ast[0][0];       // 2176 words, exactly 32*68
    #pragma unroll
    for (int pass = 0; pass < 4; pass++) {
        __syncthreads();                 // prior pass readout / mainloop done
        const int pwm = (pass >> 1) * 64;
        const int mtb = (pass & 1) * 2;
        if (wm == pwm) {
            #pragma unroll
            for (int mi = 0; mi < 2; mi++) {
                const int mt = mtb + mi;
                #pragma unroll
                for (int hf = 0; hf < 2; hf++) {
                    const int lrow = mi * 16 + hf * 8 + r;
                    #pragma unroll
                    for (int nt = 0; nt < 4; nt++) {
                        const int wcol = (wn >> 1) + nt * 4 + cc;
                        stage[lrow * 68 + wcol] =
                            pack_h2(c[mt][nt][hf * 2], c[mt][nt][hf * 2 + 1]);
                    }
                }
            }
        }
        __syncthreads();
        const int lr = tid >> 3;
        const int m = bm + pass * 32 + lr;
        if (m < NN) {
            const uint32_t* srow = stage + lr * 68 + (tid & 7) * 4;
            uint4 d0 = *(const uint4*)(srow);
            uint4 d1 = *(const uint4*)(srow + 32);
            uint4* gx = (uint4*)g_xh1h;
            gx[(size_t)m * 32 + (bn >> 3) + (tid & 7)]     = d0;
            gx[(size_t)m * 32 + (bn >> 3) + (tid & 7) + 8] = d1;
        }
    }
}

// ---------------- layer-1 aggregation FUSED with GEMM2 + layer-2 logits ----
// __launch_bounds__(512, 2): cap regs at 64/thread so 2 blocks (32 warps)
// fit per SM — the previous build's register count limited the SM to one
// block, starving the gather loop of latency-hiding warps.
__device__ __forceinline__ void acc_edge(float p, const uint4& u, float* acc) {
    float2 f;
    f = __half22float2(*(const __half2*)&u.x); acc[0] += p * f.x; acc[1] += p * f.y;
    f = __half22float2(*(const __half2*)&u.y); acc[2] += p * f.x; acc[3] += p * f.y;
    f = __half22float2(*(const __half2*)&u.z); acc[4] += p * f.x; acc[5] += p * f.y;
    f = __half22float2(*(const __half2*)&u.w); acc[6] += p * f.x; acc[7] += p * f.y;
}

__global__ void __launch_bounds__(512, 2) k_agg1(const float* __restrict__ b1,
                                                 const float* __restrict__ W2,
                                                 const float* __restrict__ as2,
                                                 const float* __restrict__ ad2) {
    __shared__ __half2 Wsh[128][32];     // 16 KB: Wsh[kp][n] = (W2[2kp][n], W2[2kp+1][n])
    __shared__ float rows[16][256];      // 16 KB
    const int tid = threadIdx.x, warp = tid >> 5, lane = tid & 31;
    for (int idx = tid; idx < 4096; idx += 512) {
        int kp = idx >> 5, n = idx & 31;
        Wsh[kp][n] = __floats2half2_rn(__ldg(&W2[(2 * kp) * 32 + n]),
                                       __ldg(&W2[(2 * kp + 1) * 32 + n]));
    }
    __syncthreads();

    // ---- phase 1: gather-softmax, adj prefetched one batch ahead ----
    const int n = blockIdx.x * 16 + warp;     // always < NN (6250*16 = NN)
    const int head = lane >> 2;
    const float edv = g_ed1[n * 8 + head];
    const int s0 = g_rowptr[n], s1 = g_rowptr[n + 1];
    const uint4* base = (const uint4*)g_xh1h;   // row stride = 32 uint4
    float acc[8] = {0.f, 0.f, 0.f, 0.f, 0.f, 0.f, 0.f, 0.f};
    float s = 0.f;
    int k = s0;
    int c0, c1, c2, c3;
    bool have = (k + 4 <= s1);
    if (have) {
        c0 = __ldg(&g_adj[k]);     c1 = __ldg(&g_adj[k + 1]);
        c2 = __ldg(&g_adj[k + 2]); c3 = __ldg(&g_adj[k + 3]);
    }
    while (have) {
        const int k2 = k + 4;
        const bool more = (k2 + 4 <= s1);
        int n0, n1, n2, n3;
        if (more) {
            n0 = __ldg(&g_adj[k2]);     n1 = __ldg(&g_adj[k2 + 1]);
            n2 = __ldg(&g_adj[k2 + 2]); n3 = __ldg(&g_adj[k2 + 3]);
        }
        float e0 = __ldg(&g_es1[c0 * 8 + head]) + edv;
        float e1 = __ldg(&g_es1[c1 * 8 + head]) + edv;
        float e2 = __ldg(&g_es1[c2 * 8 + head]) + edv;
        float e3 = __ldg(&g_es1[c3 * 8 + head]) + edv;
        uint4 u0 = __ldg(base + (size_t)c0 * 32 + lane);
        uint4 u1 = __ldg(base + (size_t)c1 * 32 + lane);
        uint4 u2 = __ldg(base + (size_t)c2 * 32 + lane);
        uint4 u3 = __ldg(base + (size_t)c3 * 32 + lane);
        e0 = e0 > 0.f ? e0 : 0.2f * e0;
        e1 = e1 > 0.f ? e1 : 0.2f * e1;
        e2 = e2 > 0.f ? e2 : 0.2f * e2;
        e3 = e3 > 0.f ? e3 : 0.2f * e3;
        float p0 = __expf(e0), p1 = __expf(e1), p2 = __expf(e2), p3 = __expf(e3);
        s += p0 + p1 + p2 + p3;
        acc_edge(p0, u0, acc);
        acc_edge(p1, u1, acc);
        acc_edge(p2, u2, acc);
        acc_edge(p3, u3, acc);
        k = k2; have = more;
        c0 = n0; c1 = n1; c2 = n2; c3 = n3;
    }
    for (; k < s1; k++) {
        int src0 = __ldg(&g_adj[k]);
        float e0 = __ldg(&g_es1[src0 * 8 + head]) + edv;
        uint4 u0 = __ldg(base + (size_t)src0 * 32 + lane);
        e0 = e0 > 0.f ? e0 : 0.2f * e0;
        float p0 = __expf(e0);
        s += p0;
        acc_edge(p0, u0, acc);
    }
    const float inv = 1.f / (s + 1e-16f);
    const int ch = lane * 8;
    float4 o0, o1;
    o0.x = fmaxf(acc[0] * inv + __ldg(&b1[ch + 0]), 0.f);
    o0.y = fmaxf(acc[1] * inv + __ldg(&b1[ch + 1]), 0.f);
    o0.z = fmaxf(acc[2] * inv + __ldg(&b1[ch + 2]), 0.f);
    o0.w = fmaxf(acc[3] * inv + __ldg(&b1[ch + 3]), 0.f);
    o1.x = fmaxf(acc[4] * inv + __ldg(&b1[ch + 4]), 0.f);
    o1.y = fmaxf(acc[5] * inv + __ldg(&b1[ch + 5]), 0.f);
    o1.z = fmaxf(acc[6] * inv + __ldg(&b1[ch + 6]), 0.f);
    o1.w = fmaxf(acc[7] * inv + __ldg(&b1[ch + 7]), 0.f);
    *(float4*)&rows[warp][ch]     = o0;
    *(float4*)&rows[warp][ch + 4] = o1;
    __syncthreads();                     // rows visible to phase-2 warps

    // ---- phase 2: warps 0-3, 4 nodes each: xh2 = h @ W2 (fp16 Ws, 4x reuse)
    if (warp < 4) {
        const int rb = warp * 4;
        float a0 = 0.f, a1 = 0.f, a2v = 0.f, a3 = 0.f;
        #pragma unroll 4
        for (int kp = 0; kp < 128; kp++) {
            float2 wv = __half22float2(Wsh[kp][lane]);
            float2 h0 = *(float2*)&rows[rb + 0][kp * 2];
            float2 h1 = *(float2*)&rows[rb + 1][kp * 2];
            float2 h2 = *(float2*)&rows[rb + 2][kp * 2];
            float2 h3 = *(float2*)&rows[rb + 3][kp * 2];
            a0  += h0.x * wv.x + h0.y * wv.y;
            a1  += h1.x * wv.x + h1.y * wv.y;
            a2v += h2.x * wv.x + h2.y * wv.y;
            a3  += h3.x * wv.x + h3.y * wv.y;
        }
        float res[4] = {a0, a1, a2v, a3};
        #pragma unroll
        for (int j = 0; j < 4; j++) {
            const int nn = blockIdx.x * 16 + rb + j;
            float a2 = res[j];
            g_xh2h[(size_t)nn * 32 + lane] = __float2half_rn(a2);
            float es = a2 * __ldg(&as2[lane]);
            float ed = a2 * __ldg(&ad2[lane]);
            #pragma unroll
            for (int off = 16; off > 0; off >>= 1) {
                es += __shfl_xor_sync(0xffffffffu, es, off);
                ed += __shfl_xor_sync(0xffffffffu, ed, off);
            }
            if (lane == 0) { g_es2[nn] = es; g_ed2[nn] = ed; }
        }
    }
}

// ---------------- layer-2 aggregation: HALF-warp per node, half2 gathers ---
__global__ void __launch_bounds__(256) k_agg2(float* __restrict__ out, const float* __restrict__ b2) {
    int gw = (blockIdx.x * blockDim.x + threadIdx.x) >> 5;
    int lane = threadIdx.x & 31;
    int sub = lane >> 4, sl = lane & 15;
    int n = gw * 2 + sub;
    if (n >= NN) return;
    float edv = g_ed2[n];
    int s0 = g_rowptr[n], s1 = g_rowptr[n + 1];
    const __half2* base = (const __half2*)g_xh2h;   // row stride = 16 half2
    float a0 = 0.f, a1 = 0.f, s = 0.f;
    int k = s0;
    for (; k + 4 <= s1; k += 4) {
        int src0 = __ldg(&g_adj[k]);
        int src1 = __ldg(&g_adj[k + 1]);
        int src2 = __ldg(&g_adj[k + 2]);
        int src3 = __ldg(&g_adj[k + 3]);
        float e0 = __ldg(&g_es2[src0]) + edv;
        float e1 = __ldg(&g_es2[src1]) + edv;
        float e2 = __ldg(&g_es2[src2]) + edv;
        float e3 = __ldg(&g_es2[src3]) + edv;
        float2 v0 = __half22float2(__ldg(base + (size_t)src0 * 16 + sl));
        float2 v1 = __half22float2(__ldg(base + (size_t)src1 * 16 + sl));
        float2 v2 = __half22float2(__ldg(base + (size_t)src2 * 16 + sl));
        float2 v3 = __half22float2(__ldg(base + (size_t)src3 * 16 + sl));
        e0 = e0 > 0.f ? e0 : 0.2f * e0;
        e1 = e1 > 0.f ? e1 : 0.2f * e1;
        e2 = e2 > 0.f ? e2 : 0.2f * e2;
        e3 = e3 > 0.f ? e3 : 0.2f * e3;
        float p0 = __expf(e0), p1 = __expf(e1), p2 = __expf(e2), p3 = __expf(e3);
        s += p0 + p1 + p2 + p3;
        a0 += p0 * v0.x + p1 * v1.x + p2 * v2.x + p3 * v3.x;
        a1 += p0 * v0.y + p1 * v1.y + p2 * v2.y + p3 * v3.y;
    }
    for (; k < s1; k++) {
        int src0 = __ldg(&g_adj[k]);
        float e0 = __ldg(&g_es2[src0]) + edv;
        float2 v0 = __half22float2(__ldg(base + (size_t)src0 * 16 + sl));
        e0 = e0 > 0.f ? e0 : 0.2f * e0;
        float p0 = __expf(e0);
        s += p0;
        a0 += p0 * v0.x;
        a1 += p0 * v0.y;
    }
    float inv = 1.f / (s + 1e-16f);
    float2 bb = *(const float2*)&b2[sl * 2];
    *(float2*)&out[(size_t)n * 32 + sl * 2] = make_float2(a0 * inv + bb.x, a1 * inv + bb.y);
}

// ---------------- launch ----------------
extern "C" void kernel_launch(void* const* d_in, const int* in_sizes, int n_in,
                              void* d_out, int out_size) {
    const float* x   = (const float*)d_in[0];
    const void*  ei  = d_in[1];
    const float* W1  = (const float*)d_in[2];
    const float* as1 = (const float*)d_in[3];
    const float* ad1 = (const float*)d_in[4];
    const float* b1  = (const float*)d_in[5];
    const float* W2  = (const float*)d_in[6];
    const float* as2 = (const float*)d_in[7];
    const float* ad2 = (const float*)d_in[8];
    const float* b2  = (const float*)d_in[9];
    float* out = (float*)d_out;

    // Fork: CSR chain on side stream, gemm1 concurrently on the main stream.
    cudaEventRecord(g_sh.evFork, 0);
    cudaStreamWaitEvent(g_sh.s2, g_sh.evFork, 0);

    k_detect<<<1, 32, 0, g_sh.s2>>>((const int*)ei);
    k_deg_count<<<(EE + 255) / 256, 256, 0, g_sh.s2>>>(ei);
    k_scan_block<<<NB, 1024, 0, g_sh.s2>>>();
    k_gemm1<<<dim3((NN + 127) / 128, 2), 256>>>(x, W1, as1, ad1);   // main stream
    k_scan_sums<<<1, 128, 0, g_sh.s2>>>();
    k_scan_add<<<NB, 1024, 0, g_sh.s2>>>();
    k_scatter<<<(ET + 255) / 256, 256, 0, g_sh.s2>>>(ei);
    cudaEventRecord(g_sh.evJoin, g_sh.s2);

    // Join: agg needs both gemm1 (main) and CSR (side).
    cudaStreamWaitEvent(0, g_sh.evJoin, 0);

    k_agg1<<<NN / 16, 512>>>(b1, W2, as2, ad2);   // fused agg1 + gemm2 (blocked)
    k_agg2<<<(NN / 2 + 7) / 8, 256>>>(out, b2);   // half-warp per node
}

// round 14
// speedup vs baseline: 1.0167x; 1.0167x over previous
#include <cuda_runtime.h>
#include <cuda_fp16.h>
#include <stdint.h>

#define NN 100000
#define EE 1600000
#define ET (EE + NN)
#define NB ((NN + 1023) / 1024)   // 98 scan blocks

// ---------------- scratch (device globals; no allocations) ----------------
__device__ __align__(16) __half2 g_xh1h[(size_t)NN * 128];  // layer1 x@W1 (fp16)
__device__ __align__(16) __half  g_xh2h[(size_t)NN * 32];   // layer2 h@W2 (fp16)
__device__ float g_es1[NN * 8];
__device__ float g_ed1[NN * 8];
__device__ float g_es2[NN];
__device__ float g_ed2[NN];
__device__ int   g_deg[NN];          // zero-init at load; re-zeroed every run
__device__ int   g_rowptr[NN + 1];
__device__ int   g_cursor[NN];
__device__ int   g_adj[ET];
__device__ int   g_bsums[NB];
__device__ int   g_is64;

// ---------------- side stream for CSR/gemm1 concurrency -------------------
namespace {
struct StreamHolder {
    cudaStream_t s2;
    cudaEvent_t evFork, evJoin;
    StreamHolder() {
        cudaStreamCreateWithFlags(&s2, cudaStreamNonBlocking);
        cudaEventCreateWithFlags(&evFork, cudaEventDisableTiming);
        cudaEventCreateWithFlags(&evJoin, cudaEventDisableTiming);
    }
};
StreamHolder g_sh;
}

// ---------------- int32/int64 edge_index handling ----------------
__global__ void k_detect(const int* __restrict__ ei) {
    if (threadIdx.x == 0) {
        int nz = 0;
        for (int i = 0; i < 256; i++) nz |= ei[2 * i + 1];
        g_is64 = (nz == 0) ? 1 : 0;
    }
}

__device__ __forceinline__ int edge_idx(const void* ei, int row, int i) {
    if (g_is64) return (int)((const long long*)ei)[(size_t)row * EE + i];
    return ((const int*)ei)[(size_t)row * EE + i];
}

// ---------------- CSR build ----------------
__global__ void k_deg_count(const void* __restrict__ ei) {
    int i = blockIdx.x * blockDim.x + threadIdx.x;
    if (i < EE) atomicAdd(&g_deg[edge_idx(ei, 1, i)], 1);
}

__global__ void k_scan_block() {
    __shared__ int sh[1024];
    int i = blockIdx.x * 1024 + threadIdx.x;
    int v = 0;
    if (i < NN) {
        v = g_deg[i] + 1;      // +1 = self-loop
        g_deg[i] = 0;          // restore zero-invariant for next run
    }
    sh[threadIdx.x] = v;
    #pragma unroll
    for (int off = 1; off < 1024; off <<= 1) {
        __syncthreads();
        int x = (threadIdx.x >= off) ? sh[threadIdx.x - off] : 0;
        __syncthreads();
        sh[threadIdx.x] += x;
    }
    if (i < NN) g_rowptr[i] = sh[threadIdx.x] - v;         // exclusive
    if (threadIdx.x == 1023) g_bsums[blockIdx.x] = sh[1023];
}

__global__ void k_scan_sums() {
    __shared__ int sh[128];
    int t = threadIdx.x;
    int v = (t < NB) ? g_bsums[t] : 0;
    sh[t] = v;
    #pragma unroll
    for (int off = 1; off < 128; off <<= 1) {
        __syncthreads();
        int x = (t >= off) ? sh[t - off] : 0;
        __syncthreads();
        sh[t] += x;
    }
    if (t < NB) g_bsums[t] = sh[t] - v;                     // exclusive
}

__global__ void k_scan_add() {
    int i = blockIdx.x * 1024 + threadIdx.x;
    if (i < NN) {
        int r = g_rowptr[i] + g_bsums[blockIdx.x];
        g_rowptr[i] = r;
        g_cursor[i] = r;
    }
    if (i == 0) g_rowptr[NN] = ET;
}

__global__ void k_scatter(const void* __restrict__ ei) {
    int i = blockIdx.x * blockDim.x + threadIdx.x;
    if (i >= ET) return;
    int s, d;
    if (i < EE) { s = edge_idx(ei, 0, i); d = edge_idx(ei, 1, i); }
    else        { s = d = i - EE; }
    int pos = atomicAdd(&g_cursor[d], 1);
    g_adj[pos] = s;
}

// ---------------- GEMM1 (fp16 tensor cores, fp32 accum) + fused logits ----
__device__ __forceinline__ uint32_t pack_h2(float a, float b) {
    __half2 h = __floats2half2_rn(a, b);
    return *(uint32_t*)&h;
}

__global__ void __launch_bounds__(256, 2) k_gemm1(const float* __restrict__ X,
                                                  const float* __restrict__ W,
                                                  const float* __restrict__ as1,
                                                  const float* __restrict__ ad1) {
    __shared__ uint32_t Ast[16][136];   // [k-pair][m]; frag bank = (8kc+m)%32
    __shared__ uint32_t Bs [16][136];   // [k-pair][n]; frag bank = (8kc+n)%32
    const int bm = blockIdx.x * 128, bn = blockIdx.y * 128;
    const int tid  = threadIdx.x;
    const int warp = tid >> 5;
    const int lane = tid & 31;
    const int wm = (warp >> 2) * 64;    // warp m-offset (0/64)
    const int wn = (warp & 3) * 32;     // warp n-offset (0/32/64/96)
    const int r  = lane >> 2;           // 0..7
    const int cc = lane & 3;            // 0..3

    float c[4][4][4];                   // [mt][nt][frag]
    #pragma unroll
    for (int i = 0; i < 4; i++)
        #pragma unroll
        for (int j = 0; j < 4; j++)
            c[i][j][0] = c[i][j][1] = c[i][j][2] = c[i][j][3] = 0.f;

    const int a_lr = tid >> 3;          // A: row within 32-row pass (0..31)
    const int a_c4 = (tid & 7) * 4;     // A: float col base (16B contiguous/lane)
    const int a_kp = (tid & 7) * 2;     // A: k-pair base
    const int b_R  = tid >> 4;          // B: k-pair row (0..15)
    const int b_n0 = (tid & 15) * 4;    // B: word col base (16B contiguous/lane)

    #pragma unroll
    for (int chunk = 0; chunk < 4; chunk++) {
        const int k0 = chunk * 32;
        {   // ---- A chunk (128 x 32 fp32): coalesced 4-line LDGs ----
            #pragma unroll
            for (int p = 0; p < 4; p++) {
                const int m = p * 32 + a_lr;
                const int gm = bm + m;
                float4 v = (gm < NN)
                    ? *(const float4*)(X + (size_t)gm * 128 + k0 + a_c4)
                    : make_float4(0.f, 0.f, 0.f, 0.f);
                Ast[a_kp][m]     = pack_h2(v.x, v.y);
                Ast[a_kp + 1][m] = pack_h2(v.z, v.w);
            }
        }
        {   // ---- B chunk (32 x 128): coalesced LDGs + conflict-free STS.128
            #pragma unroll
            for (int it = 0; it < 2; it++) {
                const int n0 = b_n0 + it * 64;
                const float* w0 = W + (size_t)(k0 + 2 * b_R)     * 256 + bn + n0;
                const float* w1 = W + (size_t)(k0 + 2 * b_R + 1) * 256 + bn + n0;
                float4 x0 = *(const float4*)w0;
                float4 x1 = *(const float4*)w1;
                uint4 u;
                u.x = pack_h2(x0.x, x1.x); u.y = pack_h2(x0.y, x1.y);
                u.z = pack_h2(x0.z, x1.z); u.w = pack_h2(x0.w, x1.w);
                *(uint4*)&Bs[b_R][n0] = u;
            }
        }
        __syncthreads();
        #pragma unroll
        for (int ks = 0; ks < 2; ks++) {
            const int kk2 = ks * 8;
            uint32_t a[4][4], b[4][2];
            #pragma unroll
            for (int mt = 0; mt < 4; mt++) {
                const int mb = wm + mt * 16 + r;
                a[mt][0] = Ast[kk2 + cc][mb];
                a[mt][1] = Ast[kk2 + cc][mb + 8];
                a[mt][2] = Ast[kk2 + cc + 4][mb];
                a[mt][3] = Ast[kk2 + cc + 4][mb + 8];
            }
            #pragma unroll
            for (int nt = 0; nt < 4; nt++) {
                const int nb = wn + nt * 8 + r;
                b[nt][0] = Bs[kk2 + cc][nb];
                b[nt][1] = Bs[kk2 + cc + 4][nb];
            }
            #pragma unroll
            for (int mt = 0; mt < 4; mt++)
                #pragma unroll
                for (int nt = 0; nt < 4; nt++)
                    asm volatile(
                        "mma.sync.aligned.m16n8k16.row.col.f32.f16.f16.f32 "
                        "{%0,%1,%2,%3},{%4,%5,%6,%7},{%8,%9},{%0,%1,%2,%3};"
                        : "+f"(c[mt][nt][0]), "+f"(c[mt][nt][1]),
                          "+f"(c[mt][nt][2]), "+f"(c[mt][nt][3])
                        : "r"(a[mt][0]), "r"(a[mt][1]), "r"(a[mt][2]), "r"(a[mt][3]),
                          "r"(b[nt][0]), "r"(b[nt][1]));
        }
        __syncthreads();
    }

    // ---- fused es/ed from fp32 accumulators (this warp's n-span = 1 head) --
    const int head = (bn + wn) >> 5;
    float av[4][2], dv[4][2];
    #pragma unroll
    for (int nt = 0; nt < 4; nt++) {
        const int n = bn + wn + nt * 8 + 2 * cc;
        av[nt][0] = __ldg(&as1[n]);     av[nt][1] = __ldg(&as1[n + 1]);
        dv[nt][0] = __ldg(&ad1[n]);     dv[nt][1] = __ldg(&ad1[n + 1]);
    }
    #pragma unroll
    for (int mt = 0; mt < 4; mt++) {
        const int m0 = bm + wm + mt * 16 + r;
        const int m1 = m0 + 8;
        float es0 = 0.f, ed0 = 0.f, es1v = 0.f, ed1v = 0.f;
        #pragma unroll
        for (int nt = 0; nt < 4; nt++) {
            es0  += c[mt][nt][0] * av[nt][0] + c[mt][nt][1] * av[nt][1];
            ed0  += c[mt][nt][0] * dv[nt][0] + c[mt][nt][1] * dv[nt][1];
            es1v += c[mt][nt][2] * av[nt][0] + c[mt][nt][3] * av[nt][1];
            ed1v += c[mt][nt][2] * dv[nt][0] + c[mt][nt][3] * dv[nt][1];
        }
        #pragma unroll
        for (int off = 1; off < 4; off <<= 1) {
            es0  += __shfl_xor_sync(0xffffffffu, es0,  off);
            ed0  += __shfl_xor_sync(0xffffffffu, ed0,  off);
            es1v += __shfl_xor_sync(0xffffffffu, es1v, off);
            ed1v += __shfl_xor_sync(0xffffffffu, ed1v, off);
        }
        if (cc == 0) {
            if (m0 < NN) { g_es1[m0 * 8 + head] = es0;  g_ed1[m0 * 8 + head] = ed0; }
            if (m1 < NN) { g_es1[m1 * 8 + head] = es1v; g_ed1[m1 * 8 + head] = ed1v; }
        }
    }

    // ---- epilogue: stage 32 output rows at a time in smem, STG.128 out ----
    uint32_t* stage = &Ast[0][0];       // 2176 words, exactly 32*68
    #pragma unroll
    for (int pass = 0; pass < 4; pass++) {
        __syncthreads();                 // prior pass readout / mainloop done
        const int pwm = (pass >> 1) * 64;
        const int mtb = (pass & 1) * 2;
        if (wm == pwm) {
            #pragma unroll
            for (int mi = 0; mi < 2; mi++) {
                const int mt = mtb + mi;
                #pragma unroll
                for (int hf = 0; hf < 2; hf++) {
                    const int lrow = mi * 16 + hf * 8 + r;
                    #pragma unroll
                    for (int nt = 0; nt < 4; nt++) {
                        const int wcol = (wn >> 1) + nt * 4 + cc;
                        stage[lrow * 68 + wcol] =
                            pack_h2(c[mt][nt][hf * 2], c[mt][nt][hf * 2 + 1]);
                    }
                }
            }
        }
        __syncthreads();
        const int lr = tid >> 3;
        const int m = bm + pass * 32 + lr;
        if (m < NN) {
            const uint32_t* srow = stage + lr * 68 + (tid & 7) * 4;
            uint4 d0 = *(const uint4*)(srow);
            uint4 d1 = *(const uint4*)(srow + 32);
            uint4* gx = (uint4*)g_xh1h;
            gx[(size_t)m * 32 + (bn >> 3) + (tid & 7)]     = d0;
            gx[(size_t)m * 32 + (bn >> 3) + (tid & 7) + 8] = d1;
        }
    }
}

// ---------------- layer-1 aggregation FUSED with GEMM2 + layer-2 logits ----
// 256 threads = 8 warps = 8 nodes per block (12500 blocks). Round-12 hot
// loop byte-for-byte; the smaller block lets ~3 blocks (24 warps) fit per SM
// at the natural register count, vs 1 block (16 warps) at 512 threads.
__device__ __forceinline__ void acc_edge(float p, const uint4& u, float* acc) {
    float2 f;
    f = __half22float2(*(const __half2*)&u.x); acc[0] += p * f.x; acc[1] += p * f.y;
    f = __half22float2(*(const __half2*)&u.y); acc[2] += p * f.x; acc[3] += p * f.y;
    f = __half22float2(*(const __half2*)&u.z); acc[4] += p * f.x; acc[5] += p * f.y;
    f = __half22float2(*(const __half2*)&u.w); acc[6] += p * f.x; acc[7] += p * f.y;
}

__global__ void __launch_bounds__(256) k_agg1(const float* __restrict__ b1,
                                              const float* __restrict__ W2,
                                              const float* __restrict__ as2,
                                              const float* __restrict__ ad2) {
    __shared__ __half2 Wsh[128][32];     // 16 KB: Wsh[kp][n] = (W2[2kp][n], W2[2kp+1][n])
    __shared__ float rows[8][256];       // 8 KB
    const int tid = threadIdx.x, warp = tid >> 5, lane = tid & 31;
    for (int idx = tid; idx < 4096; idx += 256) {
        int kp = idx >> 5, n = idx & 31;
        Wsh[kp][n] = __floats2half2_rn(__ldg(&W2[(2 * kp) * 32 + n]),
                                       __ldg(&W2[(2 * kp + 1) * 32 + n]));
    }
    __syncthreads();

    // ---- phase 1: gather-softmax for this warp's node ----
    const int n = blockIdx.x * 8 + warp;      // always < NN (12500*8 = NN)
    const int head = lane >> 2;
    const float edv = g_ed1[n * 8 + head];
    const int s0 = g_rowptr[n], s1 = g_rowptr[n + 1];
    const uint4* base = (const uint4*)g_xh1h;   // row stride = 32 uint4
    float acc[8] = {0.f, 0.f, 0.f, 0.f, 0.f, 0.f, 0.f, 0.f};
    float s = 0.f;
    int k = s0;
    for (; k + 4 <= s1; k += 4) {
        int src0 = __ldg(&g_adj[k]);
        int src1 = __ldg(&g_adj[k + 1]);
        int src2 = __ldg(&g_adj[k + 2]);
        int src3 = __ldg(&g_adj[k + 3]);
        float e0 = __ldg(&g_es1[src0 * 8 + head]) + edv;
        float e1 = __ldg(&g_es1[src1 * 8 + head]) + edv;
        float e2 = __ldg(&g_es1[src2 * 8 + head]) + edv;
        float e3 = __ldg(&g_es1[src3 * 8 + head]) + edv;
        uint4 u0 = __ldg(base + (size_t)src0 * 32 + lane);
        uint4 u1 = __ldg(base + (size_t)src1 * 32 + lane);
        uint4 u2 = __ldg(base + (size_t)src2 * 32 + lane);
        uint4 u3 = __ldg(base + (size_t)src3 * 32 + lane);
        e0 = e0 > 0.f ? e0 : 0.2f * e0;
        e1 = e1 > 0.f ? e1 : 0.2f * e1;
        e2 = e2 > 0.f ? e2 : 0.2f * e2;
        e3 = e3 > 0.f ? e3 : 0.2f * e3;
        float p0 = __expf(e0), p1 = __expf(e1), p2 = __expf(e2), p3 = __expf(e3);
        s += p0 + p1 + p2 + p3;
        acc_edge(p0, u0, acc);
        acc_edge(p1, u1, acc);
        acc_edge(p2, u2, acc);
        acc_edge(p3, u3, acc);
    }
    for (; k < s1; k++) {
        int src0 = __ldg(&g_adj[k]);
        float e0 = __ldg(&g_es1[src0 * 8 + head]) + edv;
        uint4 u0 = __ldg(base + (size_t)src0 * 32 + lane);
        e0 = e0 > 0.f ? e0 : 0.2f * e0;
        float p0 = __expf(e0);
        s += p0;
        acc_edge(p0, u0, acc);
    }
    const float inv = 1.f / (s + 1e-16f);
    const int ch = lane * 8;
    float4 o0, o1;
    o0.x = fmaxf(acc[0] * inv + __ldg(&b1[ch + 0]), 0.f);
    o0.y = fmaxf(acc[1] * inv + __ldg(&b1[ch + 1]), 0.f);
    o0.z = fmaxf(acc[2] * inv + __ldg(&b1[ch + 2]), 0.f);
    o0.w = fmaxf(acc[3] * inv + __ldg(&b1[ch + 3]), 0.f);
    o1.x = fmaxf(acc[4] * inv + __ldg(&b1[ch + 4]), 0.f);
    o1.y = fmaxf(acc[5] * inv + __ldg(&b1[ch + 5]), 0.f);
    o1.z = fmaxf(acc[6] * inv + __ldg(&b1[ch + 6]), 0.f);
    o1.w = fmaxf(acc[7] * inv + __ldg(&b1[ch + 7]), 0.f);
    *(float4*)&rows[warp][ch]     = o0;
    *(float4*)&rows[warp][ch + 4] = o1;
    __syncthreads();                     // rows visible to phase-2 warps

    // ---- phase 2: warps 0-1, 4 nodes each: xh2 = h @ W2 (fp16 Ws, 4x reuse)
    if (warp < 2) {
        const int rb = warp * 4;
        float a0 = 0.f, a1 = 0.f, a2v = 0.f, a3 = 0.f;
        #pragma unroll 4
        for (int kp = 0; kp < 128; kp++) {
            float2 wv = __half22float2(Wsh[kp][lane]);
            float2 h0 = *(float2*)&rows[rb + 0][kp * 2];
            float2 h1 = *(float2*)&rows[rb + 1][kp * 2];
            float2 h2 = *(float2*)&rows[rb + 2][kp * 2];
            float2 h3 = *(float2*)&rows[rb + 3][kp * 2];
            a0  += h0.x * wv.x + h0.y * wv.y;
            a1  += h1.x * wv.x + h1.y * wv.y;
            a2v += h2.x * wv.x + h2.y * wv.y;
            a3  += h3.x * wv.x + h3.y * wv.y;
        }
        float res[4] = {a0, a1, a2v, a3};
        #pragma unroll
        for (int j = 0; j < 4; j++) {
            const int nn = blockIdx.x * 8 + rb + j;
            float a2 = res[j];
            g_xh2h[(size_t)nn * 32 + lane] = __float2half_rn(a2);
            float es = a2 * __ldg(&as2[lane]);
            float ed = a2 * __ldg(&ad2[lane]);
            #pragma unroll
            for (int off = 16; off > 0; off >>= 1) {
                es += __shfl_xor_sync(0xffffffffu, es, off);
                ed += __shfl_xor_sync(0xffffffffu, ed, off);
            }
            if (lane == 0) { g_es2[nn] = es; g_ed2[nn] = ed; }
        }
    }
}

// ---------------- layer-2 aggregation: HALF-warp per node, half2 gathers ---
__global__ void __launch_bounds__(256) k_agg2(float* __restrict__ out, const float* __restrict__ b2) {
    int gw = (blockIdx.x * blockDim.x + threadIdx.x) >> 5;
    int lane = threadIdx.x & 31;
    int sub = lane >> 4, sl = lane & 15;
    int n = gw * 2 + sub;
    if (n >= NN) return;
    float edv = g_ed2[n];
    int s0 = g_rowptr[n], s1 = g_rowptr[n + 1];
    const __half2* base = (const __half2*)g_xh2h;   // row stride = 16 half2
    float a0 = 0.f, a1 = 0.f, s = 0.f;
    int k = s0;
    for (; k + 4 <= s1; k += 4) {
        int src0 = __ldg(&g_adj[k]);
        int src1 = __ldg(&g_adj[k + 1]);
        int src2 = __ldg(&g_adj[k + 2]);
        int src3 = __ldg(&g_adj[k + 3]);
        float e0 = __ldg(&g_es2[src0]) + edv;
        float e1 = __ldg(&g_es2[src1]) + edv;
        float e2 = __ldg(&g_es2[src2]) + edv;
        float e3 = __ldg(&g_es2[src3]) + edv;
        float2 v0 = __half22float2(__ldg(base + (size_t)src0 * 16 + sl));
        float2 v1 = __half22float2(__ldg(base + (size_t)src1 * 16 + sl));
        float2 v2 = __half22float2(__ldg(base + (size_t)src2 * 16 + sl));
        float2 v3 = __half22float2(__ldg(base + (size_t)src3 * 16 + sl));
        e0 = e0 > 0.f ? e0 : 0.2f * e0;
        e1 = e1 > 0.f ? e1 : 0.2f * e1;
        e2 = e2 > 0.f ? e2 : 0.2f * e2;
        e3 = e3 > 0.f ? e3 : 0.2f * e3;
        float p0 = __expf(e0), p1 = __expf(e1), p2 = __expf(e2), p3 = __expf(e3);
        s += p0 + p1 + p2 + p3;
        a0 += p0 * v0.x + p1 * v1.x + p2 * v2.x + p3 * v3.x;
        a1 += p0 * v0.y + p1 * v1.y + p2 * v2.y + p3 * v3.y;
    }
    for (; k < s1; k++) {
        int src0 = __ldg(&g_adj[k]);
        float e0 = __ldg(&g_es2[src0]) + edv;
        float2 v0 = __half22float2(__ldg(base + (size_t)src0 * 16 + sl));
        e0 = e0 > 0.f ? e0 : 0.2f * e0;
        float p0 = __expf(e0);
        s += p0;
        a0 += p0 * v0.x;
        a1 += p0 * v0.y;
    }
    float inv = 1.f / (s + 1e-16f);
    float2 bb = *(const float2*)&b2[sl * 2];
    *(float2*)&out[(size_t)n * 32 + sl * 2] = make_float2(a0 * inv + bb.x, a1 * inv + bb.y);
}

// ---------------- launch ----------------
extern "C" void kernel_launch(void* const* d_in, const int* in_sizes, int n_in,
                              void* d_out, int out_size) {
    const float* x   = (const float*)d_in[0];
    const void*  ei  = d_in[1];
    const float* W1  = (const float*)d_in[2];
    const float* as1 = (const float*)d_in[3];
    const float* ad1 = (const float*)d_in[4];
    const float* b1  = (const float*)d_in[5];
    const float* W2  = (const float*)d_in[6];
    const float* as2 = (const float*)d_in[7];
    const float* ad2 = (const float*)d_in[8];
    const float* b2  = (const float*)d_in[9];
    float* out = (float*)d_out;

    // Fork: CSR chain on side stream, gemm1 concurrently on the main stream.
    cudaEventRecord(g_sh.evFork, 0);
    cudaStreamWaitEvent(g_sh.s2, g_sh.evFork, 0);

    k_detect<<<1, 32, 0, g_sh.s2>>>((const int*)ei);
    k_deg_count<<<(EE + 255) / 256, 256, 0, g_sh.s2>>>(ei);
    k_scan_block<<<NB, 1024, 0, g_sh.s2>>>();
    k_gemm1<<<dim3((NN + 127) / 128, 2), 256>>>(x, W1, as1, ad1);   // main stream
    k_scan_sums<<<1, 128, 0, g_sh.s2>>>();
    k_scan_add<<<NB, 1024, 0, g_sh.s2>>>();
    k_scatter<<<(ET + 255) / 256, 256, 0, g_sh.s2>>>(ei);
    cudaEventRecord(g_sh.evJoin, g_sh.s2);

    // Join: agg needs both gemm1 (main) and CSR (side).
    cudaStreamWaitEvent(0, g_sh.evJoin, 0);

    k_agg1<<<NN / 8, 256>>>(b1, W2, as2, ad2);    // fused agg1 + gemm2 (8 nodes/block)
    k_agg2<<<(NN / 2 + 7) / 8, 256>>>(out, b2);   // half-warp per node
}

// round 15
// speedup vs baseline: 1.0833x; 1.0655x over previous
#include <cuda_runtime.h>
#include <cuda_fp16.h>
#include <stdint.h>

#define NN 100000
#define EE 1600000
#define ET (EE + NN)
#define NB ((NN + 1023) / 1024)   // 98 scan blocks

// ---------------- scratch (device globals; no allocations) ----------------
__device__ __align__(16) __half2 g_xh1h[(size_t)NN * 128];  // layer1 x@W1 (fp16)
__device__ __align__(16) __half  g_xh2h[(size_t)NN * 32];   // layer2 h@W2 (fp16)
__device__ float g_es1[NN * 8];
__device__ float g_ed1[NN * 8];
__device__ float g_es2[NN];
__device__ float g_ed2[NN];
__device__ int   g_deg[NN];          // zero-init at load; re-zeroed every run
__device__ int   g_rowptr[NN + 1];
__device__ int   g_cursor[NN];
__device__ int   g_adj[ET];
__device__ int   g_bsums[NB];
__device__ int   g_is64;

// ---------------- side stream for CSR/gemm1 concurrency -------------------
namespace {
struct StreamHolder {
    cudaStream_t s2;
    cudaEvent_t evFork, evJoin;
    StreamHolder() {
        cudaStreamCreateWithFlags(&s2, cudaStreamNonBlocking);
        cudaEventCreateWithFlags(&evFork, cudaEventDisableTiming);
        cudaEventCreateWithFlags(&evJoin, cudaEventDisableTiming);
    }
};
StreamHolder g_sh;
}

// ---------------- int32/int64 edge_index handling ----------------
__global__ void k_detect(const int* __restrict__ ei) {
    if (threadIdx.x == 0) {
        int nz = 0;
        for (int i = 0; i < 256; i++) nz |= ei[2 * i + 1];
        g_is64 = (nz == 0) ? 1 : 0;
    }
}

__device__ __forceinline__ int edge_idx(const void* ei, int row, int i) {
    if (g_is64) return (int)((const long long*)ei)[(size_t)row * EE + i];
    return ((const int*)ei)[(size_t)row * EE + i];
}

// ---------------- CSR build ----------------
__global__ void k_deg_count(const void* __restrict__ ei) {
    int i = blockIdx.x * blockDim.x + threadIdx.x;
    if (i < EE) atomicAdd(&g_deg[edge_idx(ei, 1, i)], 1);
}

__global__ void k_scan_block() {
    __shared__ int sh[1024];
    int i = blockIdx.x * 1024 + threadIdx.x;
    int v = 0;
    if (i < NN) {
        v = g_deg[i] + 1;      // +1 = self-loop
        g_deg[i] = 0;          // restore zero-invariant for next run
    }
    sh[threadIdx.x] = v;
    #pragma unroll
    for (int off = 1; off < 1024; off <<= 1) {
        __syncthreads();
        int x = (threadIdx.x >= off) ? sh[threadIdx.x - off] : 0;
        __syncthreads();
        sh[threadIdx.x] += x;
    }
    if (i < NN) g_rowptr[i] = sh[threadIdx.x] - v;         // exclusive
    if (threadIdx.x == 1023) g_bsums[blockIdx.x] = sh[1023];
}

__global__ void k_scan_sums() {
    __shared__ int sh[128];
    int t = threadIdx.x;
    int v = (t < NB) ? g_bsums[t] : 0;
    sh[t] = v;
    #pragma unroll
    for (int off = 1; off < 128; off <<= 1) {
        __syncthreads();
        int x = (t >= off) ? sh[t - off] : 0;
        __syncthreads();
        sh[t] += x;
    }
    if (t < NB) g_bsums[t] = sh[t] - v;                     // exclusive
}

__global__ void k_scan_add() {
    int i = blockIdx.x * 1024 + threadIdx.x;
    if (i < NN) {
        int r = g_rowptr[i] + g_bsums[blockIdx.x];
        g_rowptr[i] = r;
        g_cursor[i] = r;
    }
    if (i == 0) g_rowptr[NN] = ET;
}

__global__ void k_scatter(const void* __restrict__ ei) {
    int i = blockIdx.x * blockDim.x + threadIdx.x;
    if (i >= ET) return;
    int s, d;
    if (i < EE) { s = edge_idx(ei, 0, i); d = edge_idx(ei, 1, i); }
    else        { s = d = i - EE; }
    int pos = atomicAdd(&g_cursor[d], 1);
    g_adj[pos] = s;
}

// ---------------- GEMM1 (fp16 tensor cores, fp32 accum) + fused logits ----
__device__ __forceinline__ uint32_t pack_h2(float a, float b) {
    __half2 h = __floats2half2_rn(a, b);
    return *(uint32_t*)&h;
}

__global__ void __launch_bounds__(256, 2) k_gemm1(const float* __restrict__ X,
                                                  const float* __restrict__ W,
                                                  const float* __restrict__ as1,
                                                  const float* __restrict__ ad1) {
    __shared__ uint32_t Ast[16][136];   // [k-pair][m]; frag bank = (8kc+m)%32
    __shared__ uint32_t Bs [16][136];   // [k-pair][n]; frag bank = (8kc+n)%32
    const int bm = blockIdx.x * 128, bn = blockIdx.y * 128;
    const int tid  = threadIdx.x;
    const int warp = tid >> 5;
    const int lane = tid & 31;
    const int wm = (warp >> 2) * 64;    // warp m-offset (0/64)
    const int wn = (warp & 3) * 32;     // warp n-offset (0/32/64/96)
    const int r  = lane >> 2;           // 0..7
    const int cc = lane & 3;            // 0..3

    float c[4][4][4];                   // [mt][nt][frag]
    #pragma unroll
    for (int i = 0; i < 4; i++)
        #pragma unroll
        for (int j = 0; j < 4; j++)
            c[i][j][0] = c[i][j][1] = c[i][j][2] = c[i][j][3] = 0.f;

    const int a_lr = tid >> 3;          // A: row within 32-row pass (0..31)
    const int a_c4 = (tid & 7) * 4;     // A: float col base (16B contiguous/lane)
    const int a_kp = (tid & 7) * 2;     // A: k-pair base
    const int b_R  = tid >> 4;          // B: k-pair row (0..15)
    const int b_n0 = (tid & 15) * 4;    // B: word col base (16B contiguous/lane)

    #pragma unroll
    for (int chunk = 0; chunk < 4; chunk++) {
        const int k0 = chunk * 32;
        {   // ---- A chunk (128 x 32 fp32): coalesced 4-line LDGs ----
            #pragma unroll
            for (int p = 0; p < 4; p++) {
                const int m = p * 32 + a_lr;
                const int gm = bm + m;
                float4 v = (gm < NN)
                    ? *(const float4*)(X + (size_t)gm * 128 + k0 + a_c4)
                    : make_float4(0.f, 0.f, 0.f, 0.f);
                Ast[a_kp][m]     = pack_h2(v.x, v.y);
                Ast[a_kp + 1][m] = pack_h2(v.z, v.w);
            }
        }
        {   // ---- B chunk (32 x 128): coalesced LDGs + conflict-free STS.128
            #pragma unroll
            for (int it = 0; it < 2; it++) {
                const int n0 = b_n0 + it * 64;
                const float* w0 = W + (size_t)(k0 + 2 * b_R)     * 256 + bn + n0;
                const float* w1 = W + (size_t)(k0 + 2 * b_R + 1) * 256 + bn + n0;
                float4 x0 = *(const float4*)w0;
                float4 x1 = *(const float4*)w1;
                uint4 u;
                u.x = pack_h2(x0.x, x1.x); u.y = pack_h2(x0.y, x1.y);
                u.z = pack_h2(x0.z, x1.z); u.w = pack_h2(x0.w, x1.w);
                *(uint4*)&Bs[b_R][n0] = u;
            }
        }
        __syncthreads();
        #pragma unroll
        for (int ks = 0; ks < 2; ks++) {
            const int kk2 = ks * 8;
            uint32_t a[4][4], b[4][2];
            #pragma unroll
            for (int mt = 0; mt < 4; mt++) {
                const int mb = wm + mt * 16 + r;
                a[mt][0] = Ast[kk2 + cc][mb];
                a[mt][1] = Ast[kk2 + cc][mb + 8];
                a[mt][2] = Ast[kk2 + cc + 4][mb];
                a[mt][3] = Ast[kk2 + cc + 4][mb + 8];
            }
            #pragma unroll
            for (int nt = 0; nt < 4; nt++) {
                const int nb = wn + nt * 8 + r;
                b[nt][0] = Bs[kk2 + cc][nb];
                b[nt][1] = Bs[kk2 + cc + 4][nb];
            }
            #pragma unroll
            for (int mt = 0; mt < 4; mt++)
                #pragma unroll
                for (int nt = 0; nt < 4; nt++)
                    asm volatile(
                        "mma.sync.aligned.m16n8k16.row.col.f32.f16.f16.f32 "
                        "{%0,%1,%2,%3},{%4,%5,%6,%7},{%8,%9},{%0,%1,%2,%3};"
                        : "+f"(c[mt][nt][0]), "+f"(c[mt][nt][1]),
                          "+f"(c[mt][nt][2]), "+f"(c[mt][nt][3])
                        : "r"(a[mt][0]), "r"(a[mt][1]), "r"(a[mt][2]), "r"(a[mt][3]),
                          "r"(b[nt][0]), "r"(b[nt][1]));
        }
        __syncthreads();
    }

    // ---- fused es/ed from fp32 accumulators (this warp's n-span = 1 head) --
    const int head = (bn + wn) >> 5;
    float av[4][2], dv[4][2];
    #pragma unroll
    for (int nt = 0; nt < 4; nt++) {
        const int n = bn + wn + nt * 8 + 2 * cc;
        av[nt][0] = __ldg(&as1[n]);     av[nt][1] = __ldg(&as1[n + 1]);
        dv[nt][0] = __ldg(&ad1[n]);     dv[nt][1] = __ldg(&ad1[n + 1]);
    }
    #pragma unroll
    for (int mt = 0; mt < 4; mt++) {
        const int m0 = bm + wm + mt * 16 + r;
        const int m1 = m0 + 8;
        float es0 = 0.f, ed0 = 0.f, es1v = 0.f, ed1v = 0.f;
        #pragma unroll
        for (int nt = 0; nt < 4; nt++) {
            es0  += c[mt][nt][0] * av[nt][0] + c[mt][nt][1] * av[nt][1];
            ed0  += c[mt][nt][0] * dv[nt][0] + c[mt][nt][1] * dv[nt][1];
            es1v += c[mt][nt][2] * av[nt][0] + c[mt][nt][3] * av[nt][1];
            ed1v += c[mt][nt][2] * dv[nt][0] + c[mt][nt][3] * dv[nt][1];
        }
        #pragma unroll
        for (int off = 1; off < 4; off <<= 1) {
            es0  += __shfl_xor_sync(0xffffffffu, es0,  off);
            ed0  += __shfl_xor_sync(0xffffffffu, ed0,  off);
            es1v += __shfl_xor_sync(0xffffffffu, es1v, off);
            ed1v += __shfl_xor_sync(0xffffffffu, ed1v, off);
        }
        if (cc == 0) {
            if (m0 < NN) { g_es1[m0 * 8 + head] = es0;  g_ed1[m0 * 8 + head] = ed0; }
            if (m1 < NN) { g_es1[m1 * 8 + head] = es1v; g_ed1[m1 * 8 + head] = ed1v; }
        }
    }

    // ---- epilogue: stage 32 output rows at a time in smem, STG.128 out ----
    uint32_t* stage = &Ast[0][0];       // 2176 words, exactly 32*68
    #pragma unroll
    for (int pass = 0; pass < 4; pass++) {
        __syncthreads();                 // prior pass readout / mainloop done
        const int pwm = (pass >> 1) * 64;
        const int mtb = (pass & 1) * 2;
        if (wm == pwm) {
            #pragma unroll
            for (int mi = 0; mi < 2; mi++) {
                const int mt = mtb + mi;
                #pragma unroll
                for (int hf = 0; hf < 2; hf++) {
                    const int lrow = mi * 16 + hf * 8 + r;
                    #pragma unroll
                    for (int nt = 0; nt < 4; nt++) {
                        const int wcol = (wn >> 1) + nt * 4 + cc;
                        stage[lrow * 68 + wcol] =
                            pack_h2(c[mt][nt][hf * 2], c[mt][nt][hf * 2 + 1]);
                    }
                }
            }
        }
        __syncthreads();
        const int lr = tid >> 3;
        const int m = bm + pass * 32 + lr;
        if (m < NN) {
            const uint32_t* srow = stage + lr * 68 + (tid & 7) * 4;
            uint4 d0 = *(const uint4*)(srow);
            uint4 d1 = *(const uint4*)(srow + 32);
            uint4* gx = (uint4*)g_xh1h;
            gx[(size_t)m * 32 + (bn >> 3) + (tid & 7)]     = d0;
            gx[(size_t)m * 32 + (bn >> 3) + (tid & 7) + 8] = d1;
        }
    }
}

// ---------------- layer-1 aggregation FUSED with GEMM2 + layer-2 logits ----
// Round-12 version, byte-for-byte: 512 threads = 16 warps = 16 nodes/block.
__device__ __forceinline__ void acc_edge(float p, const uint4& u, float* acc) {
    float2 f;
    f = __half22float2(*(const __half2*)&u.x); acc[0] += p * f.x; acc[1] += p * f.y;
    f = __half22float2(*(const __half2*)&u.y); acc[2] += p * f.x; acc[3] += p * f.y;
    f = __half22float2(*(const __half2*)&u.z); acc[4] += p * f.x; acc[5] += p * f.y;
    f = __half22float2(*(const __half2*)&u.w); acc[6] += p * f.x; acc[7] += p * f.y;
}

__global__ void __launch_bounds__(512) k_agg1(const float* __restrict__ b1,
                                              const float* __restrict__ W2,
                                              const float* __restrict__ as2,
                                              const float* __restrict__ ad2) {
    __shared__ __half2 Wsh[128][32];     // 16 KB: Wsh[kp][n] = (W2[2kp][n], W2[2kp+1][n])
    __shared__ float rows[16][256];      // 16 KB
    const int tid = threadIdx.x, warp = tid >> 5, lane = tid & 31;
    for (int idx = tid; idx < 4096; idx += 512) {
        int kp = idx >> 5, n = idx & 31;
        Wsh[kp][n] = __floats2half2_rn(__ldg(&W2[(2 * kp) * 32 + n]),
                                       __ldg(&W2[(2 * kp + 1) * 32 + n]));
    }
    __syncthreads();

    // ---- phase 1: gather-softmax for this warp's node ----
    const int n = blockIdx.x * 16 + warp;     // probe grid=1: nodes 0..15
    const int head = lane >> 2;
    const float edv = g_ed1[n * 8 + head];
    const int s0 = g_rowptr[n], s1 = g_rowptr[n + 1];
    const uint4* base = (const uint4*)g_xh1h;   // row stride = 32 uint4
    float acc[8] = {0.f, 0.f, 0.f, 0.f, 0.f, 0.f, 0.f, 0.f};
    float s = 0.f;
    int k = s0;
    for (; k + 4 <= s1; k += 4) {
        int src0 = __ldg(&g_adj[k]);
        int src1 = __ldg(&g_adj[k + 1]);
        int src2 = __ldg(&g_adj[k + 2]);
        int src3 = __ldg(&g_adj[k + 3]);
        float e0 = __ldg(&g_es1[src0 * 8 + head]) + edv;
        float e1 = __ldg(&g_es1[src1 * 8 + head]) + edv;
        float e2 = __ldg(&g_es1[src2 * 8 + head]) + edv;
        float e3 = __ldg(&g_es1[src3 * 8 + head]) + edv;
        uint4 u0 = __ldg(base + (size_t)src0 * 32 + lane);
        uint4 u1 = __ldg(base + (size_t)src1 * 32 + lane);
        uint4 u2 = __ldg(base + (size_t)src2 * 32 + lane);
        uint4 u3 = __ldg(base + (size_t)src3 * 32 + lane);
        e0 = e0 > 0.f ? e0 : 0.2f * e0;
        e1 = e1 > 0.f ? e1 : 0.2f * e1;
        e2 = e2 > 0.f ? e2 : 0.2f * e2;
        e3 = e3 > 0.f ? e3 : 0.2f * e3;
        float p0 = __expf(e0), p1 = __expf(e1), p2 = __expf(e2), p3 = __expf(e3);
        s += p0 + p1 + p2 + p3;
        acc_edge(p0, u0, acc);
        acc_edge(p1, u1, acc);
        acc_edge(p2, u2, acc);
        acc_edge(p3, u3, acc);
    }
    for (; k < s1; k++) {
        int src0 = __ldg(&g_adj[k]);
        float e0 = __ldg(&g_es1[src0 * 8 + head]) + edv;
        uint4 u0 = __ldg(base + (size_t)src0 * 32 + lane);
        e0 = e0 > 0.f ? e0 : 0.2f * e0;
        float p0 = __expf(e0);
        s += p0;
        acc_edge(p0, u0, acc);
    }
    const float inv = 1.f / (s + 1e-16f);
    const int ch = lane * 8;
    float4 o0, o1;
    o0.x = fmaxf(acc[0] * inv + __ldg(&b1[ch + 0]), 0.f);
    o0.y = fmaxf(acc[1] * inv + __ldg(&b1[ch + 1]), 0.f);
    o0.z = fmaxf(acc[2] * inv + __ldg(&b1[ch + 2]), 0.f);
    o0.w = fmaxf(acc[3] * inv + __ldg(&b1[ch + 3]), 0.f);
    o1.x = fmaxf(acc[4] * inv + __ldg(&b1[ch + 4]), 0.f);
    o1.y = fmaxf(acc[5] * inv + __ldg(&b1[ch + 5]), 0.f);
    o1.z = fmaxf(acc[6] * inv + __ldg(&b1[ch + 6]), 0.f);
    o1.w = fmaxf(acc[7] * inv + __ldg(&b1[ch + 7]), 0.f);
    *(float4*)&rows[warp][ch]     = o0;
    *(float4*)&rows[warp][ch + 4] = o1;
    __syncthreads();                     // rows visible to phase-2 warps

    // ---- phase 2: warps 0-3, 4 nodes each: xh2 = h @ W2 (fp16 Ws, 4x reuse)
    if (warp < 4) {
        const int rb = warp * 4;
        float a0 = 0.f, a1 = 0.f, a2v = 0.f, a3 = 0.f;
        #pragma unroll 4
        for (int kp = 0; kp < 128; kp++) {
            float2 wv = __half22float2(Wsh[kp][lane]);
            float2 h0 = *(float2*)&rows[rb + 0][kp * 2];
            float2 h1 = *(float2*)&rows[rb + 1][kp * 2];
            float2 h2 = *(float2*)&rows[rb + 2][kp * 2];
            float2 h3 = *(float2*)&rows[rb + 3][kp * 2];
            a0  += h0.x * wv.x + h0.y * wv.y;
            a1  += h1.x * wv.x + h1.y * wv.y;
            a2v += h2.x * wv.x + h2.y * wv.y;
            a3  += h3.x * wv.x + h3.y * wv.y;
        }
        float res[4] = {a0, a1, a2v, a3};
        #pragma unroll
        for (int j = 0; j < 4; j++) {
            const int nn = blockIdx.x * 16 + rb + j;
            float a2 = res[j];
            g_xh2h[(size_t)nn * 32 + lane] = __float2half_rn(a2);
            float es = a2 * __ldg(&as2[lane]);
            float ed = a2 * __ldg(&ad2[lane]);
            #pragma unroll
            for (int off = 16; off > 0; off >>= 1) {
                es += __shfl_xor_sync(0xffffffffu, es, off);
                ed += __shfl_xor_sync(0xffffffffu, ed, off);
            }
            if (lane == 0) { g_es2[nn] = es; g_ed2[nn] = ed; }
        }
    }
}

// ---------------- layer-2 aggregation: HALF-warp per node, half2 gathers ---
__global__ void __launch_bounds__(256) k_agg2(float* __restrict__ out, const float* __restrict__ b2) {
    int gw = (blockIdx.x * blockDim.x + threadIdx.x) >> 5;
    int lane = threadIdx.x & 31;
    int sub = lane >> 4, sl = lane & 15;
    int n = gw * 2 + sub;
    if (n >= NN) return;
    float edv = g_ed2[n];
    int s0 = g_rowptr[n], s1 = g_rowptr[n + 1];
    const __half2* base = (const __half2*)g_xh2h;   // row stride = 16 half2
    float a0 = 0.f, a1 = 0.f, s = 0.f;
    int k = s0;
    for (; k + 4 <= s1; k += 4) {
        int src0 = __ldg(&g_adj[k]);
        int src1 = __ldg(&g_adj[k + 1]);
        int src2 = __ldg(&g_adj[k + 2]);
        int src3 = __ldg(&g_adj[k + 3]);
        float e0 = __ldg(&g_es2[src0]) + edv;
        float e1 = __ldg(&g_es2[src1]) + edv;
        float e2 = __ldg(&g_es2[src2]) + edv;
        float e3 = __ldg(&g_es2[src3]) + edv;
        float2 v0 = __half22float2(__ldg(base + (size_t)src0 * 16 + sl));
        float2 v1 = __half22float2(__ldg(base + (size_t)src1 * 16 + sl));
        float2 v2 = __half22float2(__ldg(base + (size_t)src2 * 16 + sl));
        float2 v3 = __half22float2(__ldg(base + (size_t)src3 * 16 + sl));
        e0 = e0 > 0.f ? e0 : 0.2f * e0;
        e1 = e1 > 0.f ? e1 : 0.2f * e1;
        e2 = e2 > 0.f ? e2 : 0.2f * e2;
        e3 = e3 > 0.f ? e3 : 0.2f * e3;
        float p0 = __expf(e0), p1 = __expf(e1), p2 = __expf(e2), p3 = __expf(e3);
        s += p0 + p1 + p2 + p3;
        a0 += p0 * v0.x + p1 * v1.x + p2 * v2.x + p3 * v3.x;
        a1 += p0 * v0.y + p1 * v1.y + p2 * v2.y + p3 * v3.y;
    }
    for (; k < s1; k++) {
        int src0 = __ldg(&g_adj[k]);
        float e0 = __ldg(&g_es2[src0]) + edv;
        float2 v0 = __half22float2(__ldg(base + (size_t)src0 * 16 + sl));
        e0 = e0 > 0.f ? e0 : 0.2f * e0;
        float p0 = __expf(e0);
        s += p0;
        a0 += p0 * v0.x;
        a1 += p0 * v0.y;
    }
    float inv = 1.f / (s + 1e-16f);
    float2 bb = *(const float2*)&b2[sl * 2];
    *(float2*)&out[(size_t)n * 32 + sl * 2] = make_float2(a0 * inv + bb.x, a1 * inv + bb.y);
}

// ---------------- launch ----------------
extern "C" void kernel_launch(void* const* d_in, const int* in_sizes, int n_in,
                              void* d_out, int out_size) {
    const float* x   = (const float*)d_in[0];
    const void*  ei  = d_in[1];
    const float* W1  = (const float*)d_in[2];
    const float* as1 = (const float*)d_in[3];
    const float* ad1 = (const float*)d_in[4];
    const float* b1  = (const float*)d_in[5];
    const float* W2  = (const float*)d_in[6];
    const float* as2 = (const float*)d_in[7];
    const float* ad2 = (const float*)d_in[8];
    const float* b2  = (const float*)d_in[9];
    float* out = (float*)d_out;

    // Fork: CSR chain on side stream, gemm1 concurrently on the main stream.
    cudaEventRecord(g_sh.evFork, 0);
    cudaStreamWaitEvent(g_sh.s2, g_sh.evFork, 0);

    k_detect<<<1, 32, 0, g_sh.s2>>>((const int*)ei);
    k_deg_count<<<(EE + 255) / 256, 256, 0, g_sh.s2>>>(ei);
    k_scan_block<<<NB, 1024, 0, g_sh.s2>>>();

    // PROFILING PROBE (4th submitted launch -> captured by ncu): grid=1 agg1.
    // Reads last-replay state (deterministic across replays; all-zero rowptr on
    // the first call -> no-op). Its 16 nodes are fully recomputed by the real
    // agg1 below, so output is unchanged. Cost ~3us. Gives agg1's true regs,
    // occupancy limiter, and stall mix, which rounds 13-14 lacked.
    k_agg1<<<1, 512>>>(b1, W2, as2, ad2);

    k_gemm1<<<dim3((NN + 127) / 128, 2), 256>>>(x, W1, as1, ad1);   // main stream
    k_scan_sums<<<1, 128, 0, g_sh.s2>>>();
    k_scan_add<<<NB, 1024, 0, g_sh.s2>>>();
    k_scatter<<<(ET + 255) / 256, 256, 0, g_sh.s2>>>(ei);
    cudaEventRecord(g_sh.evJoin, g_sh.s2);

    // Join: agg needs both gemm1 (main) and CSR (side).
    cudaStreamWaitEvent(0, g_sh.evJoin, 0);

    k_agg1<<<NN / 16, 512>>>(b1, W2, as2, ad2);   // fused agg1 + gemm2 (blocked)
    k_agg2<<<(NN / 2 + 7) / 8, 256>>>(out, b2);   // half-warp per node
}